// round 7
// baseline (speedup 1.0000x reference)
#include <cuda_runtime.h>

// maxF1 loss: input/target [B=16, C=4, H=512, W=512] float32.
// loss = mean_c (1 - max_k F1_c(k)),  F1 = 2*TP/(P+PP) over 1000 thresholds.
//
// Fused kernel, atomic-free mainloop:
//   idx = ceil(x*999). Warp-private histograms; per warp-instruction,
//   __match_any groups equal bins, ballot+popc aggregates (count, y_count),
//   lowest matched lane commits via non-atomic LDS+ADD+STS (branchless SEL;
//   non-leaders hit a scratch bin). Flush -> packed global hist -> last
//   block (ticket) scans, computes loss, re-zeroes state for next replay.

#define NTHRESH 1000
#define NBINS   (NTHRESH + 1)
#define HISTSZ  (NBINS + 1)            // +1 scratch bin for non-leaders
#define NBINSP  1004                   // padded global row (uint4 loads)
#define CCLS    4
#define BB      16
#define HW      (512 * 512)
#define N_PER_CLASS (BB * HW)          // 4194304
#define PLANES  (BB * CCLS)            // 64
#define SLICES  8
#define NBLOCKS (PLANES * SLICES)      // 512 (all resident @7 blocks/SM)
#define HTHREADS 256
#define NWARPS  (HTHREADS / 32)        // 8 (one private hist per warp)
#define ELEMS_PER_BLOCK (HW / SLICES)  // 32768
#define N4      (ELEMS_PER_BLOCK / 4)  // 8192

__device__ unsigned int g_hist[CCLS][NBINSP];  // count | y<<16 (pad stays 0)
__device__ unsigned int g_ticket;

__global__ __launch_bounds__(HTHREADS) void fused_kernel(
    const float* __restrict__ x, const float* __restrict__ y,
    float* __restrict__ out)
{
    __shared__ unsigned int s_hist[NWARPS][HISTSZ];
    __shared__ unsigned int s_wc[NWARPS], s_wy[NWARPS];
    __shared__ float s_m[NWARPS];
    __shared__ unsigned int s_last;

    const int tid = threadIdx.x;
    const int wid = tid >> 5;
    const int lane = tid & 31;
    const unsigned int lt = (1u << lane) - 1u;   // lanemask_lt

#pragma unroll
    for (int k = tid; k < NWARPS * HISTSZ; k += HTHREADS)
        ((unsigned int*)s_hist)[k] = 0u;
    __syncthreads();

    unsigned int* __restrict__ hb = s_hist[wid];  // warp-exclusive

    const int plane = blockIdx.x >> 3;            // / SLICES
    const int slice = blockIdx.x & (SLICES - 1);
    const int cls = plane & (CCLS - 1);           // [B,C,H,W]: plane = b*C+c
    const long long base =
        (long long)plane * HW + (long long)slice * ELEMS_PER_BLOCK;

    const float4* __restrict__ x4 = (const float4*)(x + base);
    const float4* __restrict__ y4 = (const float4*)(y + base);

    // N4 is a multiple of HTHREADS -> loop count uniform, full masks valid
#pragma unroll 2
    for (int i = tid; i < N4; i += HTHREADS) {
        float4 xv = x4[i];
        float4 yv = y4[i];
#pragma unroll
        for (int j = 0; j < 4; j++) {
            // idx = #{k : k/999 < xs} = ceil(xs*999); x in [0,1) -> <= 999
            int idx = __float2int_ru((&xv.x)[j] * 999.0f);
            // y in {0.0f,1.0f}: (bits>>13)&0x10000 == y<<16
            unsigned int yb = (__float_as_uint((&yv.x)[j]) >> 13) & 0x10000u;
            unsigned int m = __match_any_sync(0xffffffffu, idx);
            unsigned int ybal = __ballot_sync(0xffffffffu, yb != 0u);
            bool leader = (m & lt) == 0u;       // lowest lane of the group
            unsigned int agg = leader
                ? ((unsigned int)__popc(m) | ((unsigned int)__popc(m & ybal) << 16))
                : 0u;
            int tix = leader ? idx : NBINS;     // scratch bin for dups
            hb[tix] += agg;                     // LDS+IADD+STS, warp-private
        }
    }
    __syncthreads();

    for (int k = tid; k < NBINS; k += HTHREADS) {
        unsigned int v = 0;
#pragma unroll
        for (int w = 0; w < NWARPS; w++) v += s_hist[w][k];
        atomicAdd(&g_hist[cls][k], v);
    }
    __syncthreads();   // all flush atomics issued before ticket

    // ---- ticket: last block to arrive runs the epilogue ----
    if (tid == 0) {
        __threadfence();
        s_last = atomicAdd(&g_ticket, 1u);
    }
    __syncthreads();
    if (s_last != NBLOCKS - 1) return;
    __threadfence();

    // ---- epilogue: scan + F1 max + loss, 256 threads, 4 bins/thread ----
    float loss = 0.0f;
#pragma unroll 1
    for (int c = 0; c < CCLS; c++) {
        const int k0 = tid * 4;
        unsigned int vc[4], vy[4];
        if (k0 < NBINSP) {
            uint4 hv = *(const uint4*)&g_hist[c][k0];
#pragma unroll
            for (int j = 0; j < 4; j++) {
                unsigned int h = (&hv.x)[j];
                vc[j] = h & 0xffffu;
                vy[j] = h >> 16;
            }
        } else {
            vc[0] = vc[1] = vc[2] = vc[3] = 0u;
            vy[0] = vy[1] = vy[2] = vy[3] = 0u;
        }
        vc[1] += vc[0]; vc[2] += vc[1]; vc[3] += vc[2];
        vy[1] += vy[0]; vy[2] += vy[1]; vy[3] += vy[2];
        unsigned int tc = vc[3], ty = vy[3];
        unsigned int ic = tc, iy = ty;
#pragma unroll
        for (int o = 1; o < 32; o <<= 1) {
            unsigned int a = __shfl_up_sync(0xffffffffu, ic, o);
            unsigned int b = __shfl_up_sync(0xffffffffu, iy, o);
            if (lane >= o) { ic += a; iy += b; }
        }
        if (lane == 31) { s_wc[wid] = ic; s_wy[wid] = iy; }
        __syncthreads();
        if (tid == 0) {
            unsigned int ac = 0u, ay = 0u;
#pragma unroll
            for (int w = 0; w < NWARPS; w++) {
                ac += s_wc[w]; ay += s_wy[w];
                s_wc[w] = ac;  s_wy[w] = ay;
            }
        }
        __syncthreads();
        unsigned int offc = (ic - tc) + (wid ? s_wc[wid - 1] : 0u);
        unsigned int offy = (iy - ty) + (wid ? s_wy[wid - 1] : 0u);
        unsigned int P = s_wy[NWARPS - 1];

        float fmx = 0.0f;
#pragma unroll
        for (int j = 0; j < 4; j++) {
            int k = k0 + j;
            if (k < NTHRESH) {
                unsigned int TP = P - (offy + vy[j]);
                unsigned int PP = (unsigned int)N_PER_CLASS - (offc + vc[j]);
                unsigned int den = P + PP;   // 2*(TP + 0.5*(FN+FP))
                float f1 = (den == 0u) ? 0.0f
                                       : (2.0f * (float)TP) / (float)den;
                fmx = fmaxf(fmx, f1);
            }
        }
#pragma unroll
        for (int o = 16; o; o >>= 1)
            fmx = fmaxf(fmx, __shfl_xor_sync(0xffffffffu, fmx, o));
        if (lane == 0) s_m[wid] = fmx;
        __syncthreads();
        if (tid == 0) {
            float m = s_m[0];
#pragma unroll
            for (int w = 1; w < NWARPS; w++) m = fmaxf(m, s_m[w]);
            loss += 1.0f - m;
        }
        __syncthreads();
    }

    // re-zero global state for the next replay (statics start zeroed)
    for (int k = tid; k < CCLS * NBINSP; k += HTHREADS)
        ((unsigned int*)g_hist)[k] = 0u;
    if (tid == 0) {
        g_ticket = 0u;
        out[0] = loss / (float)CCLS;
    }
}

extern "C" void kernel_launch(void* const* d_in, const int* in_sizes, int n_in,
                              void* d_out, int out_size) {
    const float* x = (const float*)d_in[0];   // input
    const float* y = (const float*)d_in[1];   // target
    (void)in_sizes; (void)n_in; (void)out_size;

    fused_kernel<<<NBLOCKS, HTHREADS>>>(x, y, (float*)d_out);
}

// round 8
// speedup vs baseline: 4.5549x; 4.5549x over previous
#include <cuda_runtime.h>

// maxF1 loss: input/target [B=16, C=4, H=512, W=512] float32.
// loss = mean_c (1 - max_k F1_c(k)),  F1 = 2*TP/(P+PP) over 1000 thresholds.
//
// Pass 1 (hist, = R4 known-good): per-class 1001-bin histogram of
//   idx = ceil(x*999); 4-way shared histograms (u32 packed count|y<<16)
//   with shared atomics, flushed to packed global histogram.
// Pass 2 (f1): 4 blocks x 1024 threads, one class per block, thread-per-bin
//   block scan + F1 max; last block (ticket) combines in fixed order and
//   re-zeroes global state for the next graph replay (statics start 0).

#define NTHRESH 1000
#define NBINS   (NTHRESH + 1)
#define CCLS    4
#define BB      16
#define HW      (512 * 512)
#define N_PER_CLASS (BB * HW)          // 4194304
#define PLANES  (BB * CCLS)            // 64
#define SLICES  16
#define HTHREADS 256
#define NCOPY   4
#define ELEMS_PER_BLOCK (HW / SLICES)  // 16384
#define N4      (ELEMS_PER_BLOCK / 4)  // 4096

__device__ unsigned int g_hist[CCLS][NBINS];   // count | y<<16
__device__ float g_cmax[CCLS];
__device__ unsigned int g_ticket;

__global__ __launch_bounds__(HTHREADS) void hist_kernel(
    const float* __restrict__ x, const float* __restrict__ y)
{
    __shared__ unsigned int s_hist[NCOPY][NBINS];

    const int tid = threadIdx.x;
#pragma unroll
    for (int k = tid; k < NCOPY * NBINS; k += HTHREADS)
        ((unsigned int*)s_hist)[k] = 0u;
    __syncthreads();

    unsigned int* __restrict__ hb = s_hist[(tid >> 5) & (NCOPY - 1)];

    const int plane = blockIdx.x >> 4;           // / SLICES
    const int slice = blockIdx.x & (SLICES - 1);
    const int cls = plane & (CCLS - 1);          // [B,C,H,W]: plane = b*C + c
    const long long base =
        (long long)plane * HW + (long long)slice * ELEMS_PER_BLOCK;

    const float4* __restrict__ x4 = (const float4*)(x + base);
    const float4* __restrict__ y4 = (const float4*)(y + base);

#pragma unroll 4
    for (int i = tid; i < N4; i += HTHREADS) {
        float4 xv = x4[i];
        float4 yv = y4[i];
#pragma unroll
        for (int j = 0; j < 4; j++) {
            // idx = #{k : k/999 < xs} = ceil(xs*999); x in [0,1) -> idx <= 999
            int idx = __float2int_ru((&xv.x)[j] * 999.0f);
            // y in {0.0f,1.0f}: (bits>>13)&0x10000 == y<<16
            unsigned int yb = __float_as_uint((&yv.x)[j]);
            atomicAdd(&hb[idx], ((yb >> 13) & 0x10000u) | 1u);
        }
    }
    __syncthreads();

    for (int k = tid; k < NBINS; k += HTHREADS) {
        unsigned int v = s_hist[0][k] + s_hist[1][k] +
                         s_hist[2][k] + s_hist[3][k];
        atomicAdd(&g_hist[cls][k], v);
    }
}

__global__ __launch_bounds__(1024) void f1_kernel(float* __restrict__ out) {
    __shared__ unsigned int s_wc[32], s_wy[32];
    __shared__ float s_m[32];

    const int c = blockIdx.x;            // one class per block
    const int tid = threadIdx.x;
    const int wid = tid >> 5;
    const int lane = tid & 31;

    unsigned int h = (tid < NBINS) ? g_hist[c][tid] : 0u;
    unsigned int vc = h & 0xffffu;
    unsigned int vy = h >> 16;

    // warp inclusive scan (two independent u32 chains)
    unsigned int ic = vc, iy = vy;
#pragma unroll
    for (int o = 1; o < 32; o <<= 1) {
        unsigned int a = __shfl_up_sync(0xffffffffu, ic, o);
        unsigned int b = __shfl_up_sync(0xffffffffu, iy, o);
        if (lane >= o) { ic += a; iy += b; }
    }
    if (lane == 31) { s_wc[wid] = ic; s_wy[wid] = iy; }
    __syncthreads();
    if (wid == 0) {
        unsigned int wc = s_wc[lane], wy = s_wy[lane];
#pragma unroll
        for (int o = 1; o < 32; o <<= 1) {
            unsigned int a = __shfl_up_sync(0xffffffffu, wc, o);
            unsigned int b = __shfl_up_sync(0xffffffffu, wy, o);
            if (lane >= o) { wc += a; wy += b; }
        }
        s_wc[lane] = wc; s_wy[lane] = wy;   // inclusive warp totals
    }
    __syncthreads();

    unsigned int cumc = ic + (wid ? s_wc[wid - 1] : 0u);
    unsigned int cumy = iy + (wid ? s_wy[wid - 1] : 0u);
    unsigned int P = s_wy[31];             // total positives

    float fmx = 0.0f;
    if (tid < NTHRESH) {
        unsigned int TP = P - cumy;
        unsigned int PP = (unsigned int)N_PER_CLASS - cumc;
        unsigned int den = P + PP;          // 2*(TP + 0.5*(FN+FP))
        fmx = (den == 0u) ? 0.0f : (2.0f * (float)TP) / (float)den;
    }
#pragma unroll
    for (int o = 16; o; o >>= 1)
        fmx = fmaxf(fmx, __shfl_xor_sync(0xffffffffu, fmx, o));
    if (lane == 0) s_m[wid] = fmx;

    // re-zero this class's histogram row for the next replay
    __syncthreads();
    if (tid < NBINS) g_hist[c][tid] = 0u;

    if (wid == 0) {
        float m = s_m[lane];
#pragma unroll
        for (int o = 16; o; o >>= 1)
            m = fmaxf(m, __shfl_xor_sync(0xffffffffu, m, o));
        if (lane == 0) {
            g_cmax[c] = m;
            __threadfence();
            unsigned int t = atomicAdd(&g_ticket, 1u);
            if (t == CCLS - 1) {
                __threadfence();
                float loss = 0.0f;
#pragma unroll
                for (int k = 0; k < CCLS; k++) loss += 1.0f - g_cmax[k];
                out[0] = loss / (float)CCLS;
                g_ticket = 0u;   // reset for next replay
            }
        }
    }
}

extern "C" void kernel_launch(void* const* d_in, const int* in_sizes, int n_in,
                              void* d_out, int out_size) {
    const float* x = (const float*)d_in[0];   // input
    const float* y = (const float*)d_in[1];   // target
    (void)in_sizes; (void)n_in; (void)out_size;

    hist_kernel<<<PLANES * SLICES, HTHREADS>>>(x, y);
    f1_kernel<<<CCLS, 1024>>>((float*)d_out);
}

// round 9
// speedup vs baseline: 4.5969x; 1.0092x over previous
#include <cuda_runtime.h>

// maxF1 loss: input/target [B=16, C=4, H=512, W=512] float32.
// loss = mean_c (1 - max_k F1_c(k)),  F1 = 2*TP/(P+PP) over 1000 thresholds.
//
// Single fused kernel:
//   mainloop (= R4 known-good): per-class 1001-bin histogram of
//   idx = ceil(x*999); 4-way shared histograms (u32 packed count|y<<16)
//   with shared atomics, flushed to a packed global histogram. Streaming
//   (__ldcs) loads keep the 128MB stream from thrashing L2.
//   Epilogue: the LAST FOUR blocks (global ticket) each scan one class
//   (4 bins/thread, two u32 scans), block 4-way parallel; a second ticket
//   combines in fixed class order, writes the loss, and re-zeroes all
//   global state for the next graph replay (statics start zeroed).

#define NTHRESH 1000
#define NBINS   (NTHRESH + 1)
#define NBINSP  1004                   // padded row (16B-aligned uint4 loads)
#define CCLS    4
#define BB      16
#define HW      (512 * 512)
#define N_PER_CLASS (BB * HW)          // 4194304
#define PLANES  (BB * CCLS)            // 64
#define SLICES  16
#define NBLOCKS (PLANES * SLICES)      // 1024
#define HTHREADS 256
#define NWARPS  (HTHREADS / 32)        // 8
#define NCOPY   4
#define ELEMS_PER_BLOCK (HW / SLICES)  // 16384
#define N4      (ELEMS_PER_BLOCK / 4)  // 4096

__device__ unsigned int g_hist[CCLS][NBINSP];  // count | y<<16 (pad stays 0)
__device__ float g_cmax[CCLS];
__device__ unsigned int g_ticket;
__device__ unsigned int g_ticket2;

__global__ __launch_bounds__(HTHREADS, 8) void fused_kernel(
    const float* __restrict__ x, const float* __restrict__ y,
    float* __restrict__ out)
{
    __shared__ unsigned int s_hist[NCOPY][NBINS];
    __shared__ unsigned int s_wc[NWARPS], s_wy[NWARPS];
    __shared__ float s_m[NWARPS];
    __shared__ unsigned int s_ticket;

    const int tid = threadIdx.x;
    const int wid = tid >> 5;
    const int lane = tid & 31;

#pragma unroll
    for (int k = tid; k < NCOPY * NBINS; k += HTHREADS)
        ((unsigned int*)s_hist)[k] = 0u;
    __syncthreads();

    unsigned int* __restrict__ hb = s_hist[wid & (NCOPY - 1)];

    const int plane = blockIdx.x >> 4;           // / SLICES
    const int slice = blockIdx.x & (SLICES - 1);
    const int cls = plane & (CCLS - 1);          // [B,C,H,W]: plane = b*C + c
    const long long base =
        (long long)plane * HW + (long long)slice * ELEMS_PER_BLOCK;

    const float4* __restrict__ x4 = (const float4*)(x + base);
    const float4* __restrict__ y4 = (const float4*)(y + base);

#pragma unroll 4
    for (int i = tid; i < N4; i += HTHREADS) {
        float4 xv = __ldcs(&x4[i]);     // streaming: evict-first in L2
        float4 yv = __ldcs(&y4[i]);
#pragma unroll
        for (int j = 0; j < 4; j++) {
            // idx = #{k : k/999 < xs} = ceil(xs*999); x in [0,1) -> idx <= 999
            int idx = __float2int_ru((&xv.x)[j] * 999.0f);
            // y in {0.0f,1.0f}: (bits>>13)&0x10000 == y<<16
            unsigned int yb = __float_as_uint((&yv.x)[j]);
            atomicAdd(&hb[idx], ((yb >> 13) & 0x10000u) | 1u);
        }
    }
    __syncthreads();

    for (int k = tid; k < NBINS; k += HTHREADS) {
        unsigned int v = s_hist[0][k] + s_hist[1][k] +
                         s_hist[2][k] + s_hist[3][k];
        atomicAdd(&g_hist[cls][k], v);
    }
    __threadfence();   // make this block's flush globally visible
    __syncthreads();

    // ---- ticket: last 4 blocks each run one class's epilogue ----
    if (tid == 0) s_ticket = atomicAdd(&g_ticket, 1u);
    __syncthreads();
    const unsigned int t = s_ticket;
    if (t < NBLOCKS - CCLS) return;
    const int ce = (int)(NBLOCKS - 1u - t);      // class 0..3
    __threadfence();                              // acquire all flushes

    // ---- epilogue: one class, 256 threads, 4 bins/thread ----
    const int k0 = tid * 4;
    unsigned int vc[4] = {0u, 0u, 0u, 0u}, vy[4] = {0u, 0u, 0u, 0u};
    if (k0 < NBINSP) {
        uint4 hv = *(const uint4*)&g_hist[ce][k0];
#pragma unroll
        for (int j = 0; j < 4; j++) {
            unsigned int h = (&hv.x)[j];
            vc[j] = h & 0xffffu;
            vy[j] = h >> 16;
        }
    }
    vc[1] += vc[0]; vc[2] += vc[1]; vc[3] += vc[2];
    vy[1] += vy[0]; vy[2] += vy[1]; vy[3] += vy[2];
    unsigned int tc = vc[3], ty = vy[3];
    unsigned int ic = tc, iy = ty;
#pragma unroll
    for (int o = 1; o < 32; o <<= 1) {
        unsigned int a = __shfl_up_sync(0xffffffffu, ic, o);
        unsigned int b = __shfl_up_sync(0xffffffffu, iy, o);
        if (lane >= o) { ic += a; iy += b; }
    }
    if (lane == 31) { s_wc[wid] = ic; s_wy[wid] = iy; }
    __syncthreads();
    if (tid == 0) {
        unsigned int ac = 0u, ay = 0u;
#pragma unroll
        for (int w = 0; w < NWARPS; w++) {
            ac += s_wc[w]; ay += s_wy[w];
            s_wc[w] = ac;  s_wy[w] = ay;   // inclusive warp totals
        }
    }
    __syncthreads();
    unsigned int offc = (ic - tc) + (wid ? s_wc[wid - 1] : 0u);
    unsigned int offy = (iy - ty) + (wid ? s_wy[wid - 1] : 0u);
    unsigned int P = s_wy[NWARPS - 1];   // total positives

    float fmx = 0.0f;
#pragma unroll
    for (int j = 0; j < 4; j++) {
        int k = k0 + j;
        if (k < NTHRESH) {
            unsigned int TP = P - (offy + vy[j]);
            unsigned int PP = (unsigned int)N_PER_CLASS - (offc + vc[j]);
            unsigned int den = P + PP;     // 2*(TP + 0.5*(FN+FP))
            float f1 = (den == 0u) ? 0.0f
                                   : (2.0f * (float)TP) / (float)den;
            fmx = fmaxf(fmx, f1);
        }
    }
#pragma unroll
    for (int o = 16; o; o >>= 1)
        fmx = fmaxf(fmx, __shfl_xor_sync(0xffffffffu, fmx, o));
    if (lane == 0) s_m[wid] = fmx;
    __syncthreads();

    // re-zero this class's histogram row for the next replay
    for (int k = tid; k < NBINSP; k += HTHREADS) g_hist[ce][k] = 0u;

    if (tid == 0) {
        float m = s_m[0];
#pragma unroll
        for (int w = 1; w < NWARPS; w++) m = fmaxf(m, s_m[w]);
        g_cmax[ce] = m;
        __threadfence();
        unsigned int t2 = atomicAdd(&g_ticket2, 1u);
        if (t2 == CCLS - 1) {
            __threadfence();
            float loss = 0.0f;
#pragma unroll
            for (int c = 0; c < CCLS; c++) loss += 1.0f - g_cmax[c];
            out[0] = loss / (float)CCLS;
            g_ticket = 0u;     // reset for next replay
            g_ticket2 = 0u;
        }
    }
}

extern "C" void kernel_launch(void* const* d_in, const int* in_sizes, int n_in,
                              void* d_out, int out_size) {
    const float* x = (const float*)d_in[0];   // input
    const float* y = (const float*)d_in[1];   // target
    (void)in_sizes; (void)n_in; (void)out_size;

    fused_kernel<<<NBLOCKS, HTHREADS>>>(x, y, (float*)d_out);
}